// round 4
// baseline (speedup 1.0000x reference)
#include <cuda_runtime.h>
#include <cuda_bf16.h>
#include <cstdint>

// Problem constants (fixed by setup_inputs)
#define BH    32          // B*H
#define LSEQ  4096
#define DDIM  64
#define NBLK  64          // nQ = nK = L/64
#define TK    6           // top-k key blocks per query block
#define STR   68          // padded shared stride (float4-aligned, conflict-friendly)
#define ATT_SCALE 0.125f  // 1/sqrt(64)

typedef unsigned long long ull;

// ---------------- f32x2 packed math helpers (Blackwell) ----------------
__device__ __forceinline__ ull fma2(ull a, ull b, ull c) {
    ull d; asm("fma.rn.f32x2 %0,%1,%2,%3;" : "=l"(d) : "l"(a), "l"(b), "l"(c)); return d;
}
__device__ __forceinline__ ull mul2(ull a, ull b) {
    ull d; asm("mul.rn.f32x2 %0,%1,%2;" : "=l"(d) : "l"(a), "l"(b)); return d;
}
__device__ __forceinline__ ull splat2(float a) {
    ull r; asm("mov.b64 %0,{%1,%1};" : "=l"(r) : "f"(a)); return r;
}
__device__ __forceinline__ void upk2(ull x, float& a, float& b) {
    asm("mov.b64 {%0,%1},%2;" : "=f"(a), "=f"(b) : "l"(x));
}

// ---------------- device scratch (no dynamic allocation allowed) ----------------
__device__ float g_qmean[BH * NBLK * DDIM];
__device__ float g_kmean[BH * NBLK * DDIM];
__device__ int   g_lut[BH * NBLK * TK];
__device__ float g_kv[(size_t)BH * NBLK * DDIM * DDIM];   // 32 MB: per-block phi(k)^T v
__device__ float g_z[BH * NBLK * DDIM];
__device__ float g_kvtot[BH * DDIM * DDIM];
__device__ float g_ztot[BH * DDIM];

// ================= K1: mean-pool q and k into blocks =================
// grid (BH*NBLK, 2), block 64
__global__ void pool_kernel(const float* __restrict__ q, const float* __restrict__ k) {
    const int blk = blockIdx.x;                 // bh*64 + block index
    const float* src = blockIdx.y ? k : q;
    float* dst = blockIdx.y ? g_kmean : g_qmean;
    const int d = threadIdx.x;
    const float* p = src + (size_t)blk * (64 * DDIM) + d;
    float s = 0.f;
#pragma unroll
    for (int m = 0; m < 64; m++) s += p[m * DDIM];
    dst[blk * DDIM + d] = s * (1.f / 64.f);
}

// ================= K2: block scores + top-6 selection =================
// grid BH*NBLK, block 64
__global__ void topk_kernel() {
    __shared__ float km[64 * 65];
    __shared__ float qv[64];
    __shared__ float sc[64];
    const int bh = blockIdx.x >> 6, qi = blockIdx.x & 63;
    const int tid = threadIdx.x;
    for (int i = tid; i < 4096; i += 64) km[(i >> 6) * 65 + (i & 63)] = g_kmean[bh * 4096 + i];
    qv[tid] = g_qmean[bh * 4096 + qi * 64 + tid];
    __syncthreads();
    float s = 0.f;
#pragma unroll
    for (int d = 0; d < 64; d++) s += qv[d] * km[tid * 65 + d];
    sc[tid] = s;   // positive scale does not change ranking
    __syncthreads();
    if (tid == 0) {
        int* lp = &g_lut[(bh * 64 + qi) * TK];
#pragma unroll
        for (int t = 0; t < TK; t++) {
            float best = -1e38f; int bi = 0;
            for (int i = 0; i < 64; i++) { if (sc[i] > best) { best = sc[i]; bi = i; } }
            lp[t] = bi; sc[bi] = -1e38f;
        }
    }
}

// ================= K3: per key-block kv = phi(k)^T v and z = sum phi(k) =================
// grid BH*NBLK, block 256
__global__ void __launch_bounds__(256) kv_kernel(const float* __restrict__ k, const float* __restrict__ v) {
    __shared__ __align__(16) float Ks[64 * 65];
    __shared__ __align__(16) float Vs[64 * STR];
    const int tid = threadIdx.x;
    const size_t base = (size_t)blockIdx.x * 4096;
    for (int i = tid; i < 4096; i += 256)
        Ks[(i >> 6) * 65 + (i & 63)] = k[base + i];
    for (int i4 = tid; i4 < 1024; i4 += 256) {
        int c = i4 >> 4, e = (i4 & 15) * 4;
        *(float4*)&Vs[c * STR + e] = *(const float4*)&v[base + c * 64 + e];
    }
    __syncthreads();
    if (tid < 64) {                       // row softmax of K block (phi)
        float* row = &Ks[tid * 65];
        float mx = -1e30f;
#pragma unroll
        for (int i = 0; i < 64; i++) mx = fmaxf(mx, row[i]);
        float s = 0.f;
#pragma unroll
        for (int i = 0; i < 64; i++) { float e = __expf(row[i] - mx); row[i] = e; s += e; }
        float inv = 1.f / s;
#pragma unroll
        for (int i = 0; i < 64; i++) row[i] *= inv;
    }
    __syncthreads();
    if (tid < 64) {                       // z column sums
        float s = 0.f;
#pragma unroll
        for (int m = 0; m < 64; m++) s += Ks[m * 65 + tid];
        g_z[(size_t)blockIdx.x * 64 + tid] = s;
    }
    const int d = tid >> 2, e0 = (tid & 3) * 16;
    ull acc[8];
#pragma unroll
    for (int i = 0; i < 8; i++) acc[i] = 0ull;
#pragma unroll 4
    for (int m = 0; m < 64; m++) {
        ull cc = splat2(Ks[m * 65 + d]);
        const ull* vp = (const ull*)&Vs[m * STR + e0];
#pragma unroll
        for (int t = 0; t < 8; t++) acc[t] = fma2(cc, vp[t], acc[t]);
    }
    ull* op = (ull*)&g_kv[(size_t)blockIdx.x * 4096 + d * 64 + e0];
#pragma unroll
    for (int t = 0; t < 8; t++) op[t] = acc[t];
}

// ================= K4: totals over key blocks =================
// grid (BH, 16), block 256
__global__ void total_kernel() {
    const int bh = blockIdx.x;
    const int o = blockIdx.y * 256 + threadIdx.x;   // 0..4095
    const float* p = &g_kv[(size_t)bh * NBLK * 4096 + o];
    float s = 0.f;
#pragma unroll 8
    for (int b = 0; b < NBLK; b++) s += p[(size_t)b * 4096];
    g_kvtot[bh * 4096 + o] = s;
    if (blockIdx.y == 0 && threadIdx.x < 64) {
        float z = 0.f;
#pragma unroll
        for (int b = 0; b < NBLK; b++) z += g_z[((size_t)bh * NBLK + b) * 64 + threadIdx.x];
        g_ztot[bh * 64 + threadIdx.x] = z;
    }
}

// ================= K5: fused sparse flash attention + linear path + projection =================
// grid BH*NBLK, block 256, ~70 KB dynamic smem
__global__ void __launch_bounds__(256) attn_kernel(
    const float* __restrict__ q, const float* __restrict__ k, const float* __restrict__ v,
    const float* __restrict__ Wl, const float* __restrict__ bl, float* __restrict__ out)
{
    extern __shared__ float sm[];
    float* Qt  = sm;                 // [d][r] stride STR  (q transposed; later phi(q) transposed)
    float* Bs  = Qt + 64 * STR;      // K^T [d][c] / V [c][e] / KVns [d][e]
    float* Ps  = Bs + 64 * STR;      // P natural [r][c] / Ol natural [r][d]
    float* Wlt = Ps + 64 * STR;      // [d][c] : Wlt[d*STR+c] = W_l[c][d]
    float* zns = Wlt + 64 * STR;     // 64
    int*   lut = (int*)(zns + 64);   // 6

    const int tid = threadIdx.x;
    const int bh = blockIdx.x >> 6, qi = blockIdx.x & 63;
    const int tr = tid >> 4, tc = tid & 15;
    const int r0 = tr * 4, c0 = tc * 4;
    const size_t qbase = ((size_t)bh * LSEQ + qi * 64) * DDIM;

    // load Q (transposed) and W_l (transposed)
    for (int i = tid; i < 4096; i += 256) {
        int a = i >> 6, b = i & 63;
        Qt[b * STR + a]  = q[qbase + i];
        Wlt[b * STR + a] = Wl[i];
    }
    if (tid < TK) lut[tid] = g_lut[(bh * 64 + qi) * TK + tid];
    __syncthreads();

    float mrow[4], lrow[4];
    ull O01[4], O23[4];
#pragma unroll
    for (int i = 0; i < 4; i++) { mrow[i] = -1e30f; lrow[i] = 0.f; O01[i] = 0ull; O23[i] = 0ull; }

    for (int j = 0; j < TK; j++) {
        const size_t kbase = ((size_t)bh * LSEQ + lut[j] * 64) * DDIM;
        // K transposed into Bs
        for (int i = tid; i < 4096; i += 256) {
            int c = i >> 6, d = i & 63;
            Bs[d * STR + c] = k[kbase + i];
        }
        __syncthreads();
        // S = scale * Q K^T (4x4 register tile, f32x2 packed)
        ull s01[4], s23[4];
#pragma unroll
        for (int i = 0; i < 4; i++) { s01[i] = 0ull; s23[i] = 0ull; }
#pragma unroll 4
        for (int d = 0; d < 64; d++) {
            float4 qv = *(const float4*)&Qt[d * STR + r0];
            ulonglong2 kv = *(const ulonglong2*)&Bs[d * STR + c0];
            ull w;
            w = splat2(qv.x); s01[0] = fma2(w, kv.x, s01[0]); s23[0] = fma2(w, kv.y, s23[0]);
            w = splat2(qv.y); s01[1] = fma2(w, kv.x, s01[1]); s23[1] = fma2(w, kv.y, s23[1]);
            w = splat2(qv.z); s01[2] = fma2(w, kv.x, s01[2]); s23[2] = fma2(w, kv.y, s23[2]);
            w = splat2(qv.w); s01[3] = fma2(w, kv.x, s01[3]); s23[3] = fma2(w, kv.y, s23[3]);
        }
        // online softmax update per row
#pragma unroll
        for (int ri = 0; ri < 4; ri++) {
            float sa, sb, sc2, sd;
            upk2(s01[ri], sa, sb); upk2(s23[ri], sc2, sd);
            sa *= ATT_SCALE; sb *= ATT_SCALE; sc2 *= ATT_SCALE; sd *= ATT_SCALE;
            float rm = fmaxf(fmaxf(sa, sb), fmaxf(sc2, sd));
            rm = fmaxf(rm, __shfl_xor_sync(0xffffffffu, rm, 1));
            rm = fmaxf(rm, __shfl_xor_sync(0xffffffffu, rm, 2));
            rm = fmaxf(rm, __shfl_xor_sync(0xffffffffu, rm, 4));
            rm = fmaxf(rm, __shfl_xor_sync(0xffffffffu, rm, 8));
            float nm = fmaxf(mrow[ri], rm);
            float corr = __expf(mrow[ri] - nm);
            mrow[ri] = nm;
            float pa = __expf(sa - nm), pb = __expf(sb - nm);
            float pc = __expf(sc2 - nm), pd = __expf(sd - nm);
            float ps = pa + pb + pc + pd;
            ps += __shfl_xor_sync(0xffffffffu, ps, 1);
            ps += __shfl_xor_sync(0xffffffffu, ps, 2);
            ps += __shfl_xor_sync(0xffffffffu, ps, 4);
            ps += __shfl_xor_sync(0xffffffffu, ps, 8);
            lrow[ri] = lrow[ri] * corr + ps;
            ull cc = splat2(corr);
            O01[ri] = mul2(O01[ri], cc); O23[ri] = mul2(O23[ri], cc);
            *(float4*)&Ps[(r0 + ri) * STR + c0] = make_float4(pa, pb, pc, pd);
        }
        __syncthreads();
        // V into Bs (natural layout)
        for (int i4 = tid; i4 < 1024; i4 += 256) {
            int c = i4 >> 4, e = (i4 & 15) * 4;
            *(float4*)&Bs[c * STR + e] = *(const float4*)&v[kbase + c * 64 + e];
        }
        __syncthreads();
        // O += P V
#pragma unroll 2
        for (int c = 0; c < 64; c++) {
            ulonglong2 vv = *(const ulonglong2*)&Bs[c * STR + c0];
            float p0 = Ps[(r0 + 0) * STR + c];
            float p1 = Ps[(r0 + 1) * STR + c];
            float p2 = Ps[(r0 + 2) * STR + c];
            float p3 = Ps[(r0 + 3) * STR + c];
            ull w;
            w = splat2(p0); O01[0] = fma2(w, vv.x, O01[0]); O23[0] = fma2(w, vv.y, O23[0]);
            w = splat2(p1); O01[1] = fma2(w, vv.x, O01[1]); O23[1] = fma2(w, vv.y, O23[1]);
            w = splat2(p2); O01[2] = fma2(w, vv.x, O01[2]); O23[2] = fma2(w, vv.y, O23[2]);
            w = splat2(p3); O01[3] = fma2(w, vv.x, O01[3]); O23[3] = fma2(w, vv.y, O23[3]);
        }
        __syncthreads();
    }
    // normalize sparse output
#pragma unroll
    for (int ri = 0; ri < 4; ri++) {
        ull inv = splat2(1.f / lrow[ri]);
        O01[ri] = mul2(O01[ri], inv); O23[ri] = mul2(O23[ri], inv);
    }

    // ---------- linear path ----------
    // KVns = kvtot - sum(selected kv) -> Bs natural [d][e]
    {
        const float* kvt = &g_kvtot[bh * 4096];
        const float* kvb = &g_kv[(size_t)bh * NBLK * 4096];
        const int o = tid * 16, d = o >> 6, e = o & 63;
#pragma unroll
        for (int u = 0; u < 4; u++) {
            float4 a = *(const float4*)&kvt[o + 4 * u];
#pragma unroll
            for (int j = 0; j < TK; j++) {
                float4 b4 = *(const float4*)&kvb[(size_t)lut[j] * 4096 + o + 4 * u];
                a.x -= b4.x; a.y -= b4.y; a.z -= b4.z; a.w -= b4.w;
            }
            *(float4*)&Bs[d * STR + e + 4 * u] = a;
        }
    }
    if (tid < 64) {
        float zz = g_ztot[bh * 64 + tid];
#pragma unroll
        for (int j = 0; j < TK; j++) zz -= g_z[((size_t)bh * NBLK + lut[j]) * 64 + tid];
        zns[tid] = zz;
    }
    // phi(q): in-place row softmax on Qt columns
    if (tid < 64) {
        const int r = tid;
        float mx = -1e30f;
#pragma unroll
        for (int d = 0; d < 64; d++) mx = fmaxf(mx, Qt[d * STR + r]);
        float s = 0.f;
#pragma unroll
        for (int d = 0; d < 64; d++) { float e2 = __expf(Qt[d * STR + r] - mx); Qt[d * STR + r] = e2; s += e2; }
        float inv = 1.f / s;
#pragma unroll
        for (int d = 0; d < 64; d++) Qt[d * STR + r] *= inv;
    }
    __syncthreads();
    // num = phi(q) @ KVns ; den = phi(q) . zns ; Ol = num/(den+1e-6)
    {
        ull n01[4], n23[4]; float den[4];
#pragma unroll
        for (int i = 0; i < 4; i++) { n01[i] = 0ull; n23[i] = 0ull; den[i] = 0.f; }
#pragma unroll 4
        for (int d = 0; d < 64; d++) {
            float4 cq = *(const float4*)&Qt[d * STR + r0];
            ulonglong2 kv = *(const ulonglong2*)&Bs[d * STR + c0];
            float zd = zns[d];
            ull w;
            w = splat2(cq.x); n01[0] = fma2(w, kv.x, n01[0]); n23[0] = fma2(w, kv.y, n23[0]); den[0] = fmaf(cq.x, zd, den[0]);
            w = splat2(cq.y); n01[1] = fma2(w, kv.x, n01[1]); n23[1] = fma2(w, kv.y, n23[1]); den[1] = fmaf(cq.y, zd, den[1]);
            w = splat2(cq.z); n01[2] = fma2(w, kv.x, n01[2]); n23[2] = fma2(w, kv.y, n23[2]); den[2] = fmaf(cq.z, zd, den[2]);
            w = splat2(cq.w); n01[3] = fma2(w, kv.x, n01[3]); n23[3] = fma2(w, kv.y, n23[3]); den[3] = fmaf(cq.w, zd, den[3]);
        }
#pragma unroll
        for (int ri = 0; ri < 4; ri++) {
            float inv = 1.f / (den[ri] + 1e-6f);
            float a, b, c2, d2; upk2(n01[ri], a, b); upk2(n23[ri], c2, d2);
            *(float4*)&Ps[(r0 + ri) * STR + c0] = make_float4(a * inv, b * inv, c2 * inv, d2 * inv);
        }
    }
    __syncthreads();
    // out = O_sparse + Ol @ Wl^T + bl
    {
        ull a01[4], a23[4];
#pragma unroll
        for (int i = 0; i < 4; i++) { a01[i] = O01[i]; a23[i] = O23[i]; }
#pragma unroll 4
        for (int d = 0; d < 64; d++) {
            ulonglong2 wv = *(const ulonglong2*)&Wlt[d * STR + c0];
            float o0 = Ps[(r0 + 0) * STR + d];
            float o1 = Ps[(r0 + 1) * STR + d];
            float o2 = Ps[(r0 + 2) * STR + d];
            float o3 = Ps[(r0 + 3) * STR + d];
            ull w;
            w = splat2(o0); a01[0] = fma2(w, wv.x, a01[0]); a23[0] = fma2(w, wv.y, a23[0]);
            w = splat2(o1); a01[1] = fma2(w, wv.x, a01[1]); a23[1] = fma2(w, wv.y, a23[1]);
            w = splat2(o2); a01[2] = fma2(w, wv.x, a01[2]); a23[2] = fma2(w, wv.y, a23[2]);
            w = splat2(o3); a01[3] = fma2(w, wv.x, a01[3]); a23[3] = fma2(w, wv.y, a23[3]);
        }
        float4 bv = *(const float4*)&bl[c0];
#pragma unroll
        for (int ri = 0; ri < 4; ri++) {
            float a, b, c2, d2; upk2(a01[ri], a, b); upk2(a23[ri], c2, d2);
            *(float4*)&out[qbase + (size_t)(r0 + ri) * 64 + c0] =
                make_float4(a + bv.x, b + bv.y, c2 + bv.z, d2 + bv.w);
        }
    }
}

// ================= launcher =================
extern "C" void kernel_launch(void* const* d_in, const int* in_sizes, int n_in,
                              void* d_out, int out_size) {
    const float* q  = (const float*)d_in[0];
    const float* k  = (const float*)d_in[1];
    const float* v  = (const float*)d_in[2];
    const float* Wl = (const float*)d_in[3];
    const float* bl = (const float*)d_in[4];
    float* out = (float*)d_out;

    const int smem_bytes = (4 * 64 * STR + 64 + 8) * (int)sizeof(float);  // 69,920 B
    cudaFuncSetAttribute(attn_kernel, cudaFuncAttributeMaxDynamicSharedMemorySize, smem_bytes);

    pool_kernel<<<dim3(BH * NBLK, 2), 64>>>(q, k);
    topk_kernel<<<BH * NBLK, 64>>>();
    kv_kernel<<<BH * NBLK, 256>>>(k, v);
    total_kernel<<<dim3(BH, 16), 256>>>();
    attn_kernel<<<BH * NBLK, 256, smem_bytes>>>(q, k, v, Wl, bl, out);
}

// round 5
// speedup vs baseline: 1.0211x; 1.0211x over previous
#include <cuda_runtime.h>
#include <cuda_bf16.h>
#include <cstdint>

// Problem constants (fixed by setup_inputs)
#define BH    32          // B*H
#define LSEQ  4096
#define DDIM  64
#define NBLK  64          // nQ = nK = L/64
#define TK    6           // top-k key blocks per query block
#define STR   68          // padded shared stride (float4-aligned)
#define ATT_SCALE 0.125f  // 1/sqrt(64)

typedef unsigned long long ull;

// ---------------- f32x2 packed math helpers (Blackwell) ----------------
__device__ __forceinline__ ull fma2(ull a, ull b, ull c) {
    ull d; asm("fma.rn.f32x2 %0,%1,%2,%3;" : "=l"(d) : "l"(a), "l"(b), "l"(c)); return d;
}
__device__ __forceinline__ ull mul2(ull a, ull b) {
    ull d; asm("mul.rn.f32x2 %0,%1,%2;" : "=l"(d) : "l"(a), "l"(b)); return d;
}
__device__ __forceinline__ ull splat2(float a) {
    ull r; asm("mov.b64 %0,{%1,%1};" : "=l"(r) : "f"(a)); return r;
}
__device__ __forceinline__ void upk2(ull x, float& a, float& b) {
    asm("mov.b64 {%0,%1},%2;" : "=f"(a), "=f"(b) : "l"(x));
}

// ---------------- device scratch (no dynamic allocation allowed) ----------------
__device__ float g_qmean[BH * NBLK * DDIM];
__device__ float g_kmean[BH * NBLK * DDIM];
__device__ int   g_lut[BH * NBLK * TK];
__device__ float g_kv[(size_t)BH * NBLK * DDIM * DDIM];   // 32 MB: per-block phi(k)^T v
__device__ float g_z[BH * NBLK * DDIM];
__device__ float g_kvtot[BH * DDIM * DDIM];
__device__ float g_ztot[BH * DDIM];

// ================= K1: mean-pool q and k into blocks =================
__global__ void pool_kernel(const float* __restrict__ q, const float* __restrict__ k) {
    const int blk = blockIdx.x;
    const float* src = blockIdx.y ? k : q;
    float* dst = blockIdx.y ? g_kmean : g_qmean;
    const int d = threadIdx.x;
    const float* p = src + (size_t)blk * (64 * DDIM) + d;
    float s = 0.f;
#pragma unroll
    for (int m = 0; m < 64; m++) s += p[m * DDIM];
    dst[blk * DDIM + d] = s * (1.f / 64.f);
}

// ================= K2: block scores + top-6 selection =================
__global__ void topk_kernel() {
    __shared__ float km[64 * 65];
    __shared__ float qv[64];
    __shared__ float sc[64];
    const int bh = blockIdx.x >> 6, qi = blockIdx.x & 63;
    const int tid = threadIdx.x;
    for (int i = tid; i < 4096; i += 64) km[(i >> 6) * 65 + (i & 63)] = g_kmean[bh * 4096 + i];
    qv[tid] = g_qmean[bh * 4096 + qi * 64 + tid];
    __syncthreads();
    float s = 0.f;
#pragma unroll
    for (int d = 0; d < 64; d++) s += qv[d] * km[tid * 65 + d];
    sc[tid] = s;
    __syncthreads();
    if (tid == 0) {
        int* lp = &g_lut[(bh * 64 + qi) * TK];
#pragma unroll
        for (int t = 0; t < TK; t++) {
            float best = -1e38f; int bi = 0;
            for (int i = 0; i < 64; i++) { if (sc[i] > best) { best = sc[i]; bi = i; } }
            lp[t] = bi; sc[bi] = -1e38f;
        }
    }
}

// ================= K3: per key-block kv = phi(k)^T v and z = sum phi(k) =================
__global__ void __launch_bounds__(256) kv_kernel(const float* __restrict__ k, const float* __restrict__ v) {
    __shared__ __align__(16) float Ks[64 * 65];
    __shared__ __align__(16) float Vs[64 * STR];
    const int tid = threadIdx.x;
    const size_t base = (size_t)blockIdx.x * 4096;
    for (int i = tid; i < 4096; i += 256)
        Ks[(i >> 6) * 65 + (i & 63)] = k[base + i];
    for (int i4 = tid; i4 < 1024; i4 += 256) {
        int c = i4 >> 4, e = (i4 & 15) * 4;
        *(float4*)&Vs[c * STR + e] = *(const float4*)&v[base + c * 64 + e];
    }
    __syncthreads();
    if (tid < 64) {
        float* row = &Ks[tid * 65];
        float mx = -1e30f;
#pragma unroll
        for (int i = 0; i < 64; i++) mx = fmaxf(mx, row[i]);
        float s = 0.f;
#pragma unroll
        for (int i = 0; i < 64; i++) { float e = __expf(row[i] - mx); row[i] = e; s += e; }
        float inv = 1.f / s;
#pragma unroll
        for (int i = 0; i < 64; i++) row[i] *= inv;
    }
    __syncthreads();
    if (tid < 64) {
        float s = 0.f;
#pragma unroll
        for (int m = 0; m < 64; m++) s += Ks[m * 65 + tid];
        g_z[(size_t)blockIdx.x * 64 + tid] = s;
    }
    const int d = tid >> 2, e0 = (tid & 3) * 16;
    ull acc[8];
#pragma unroll
    for (int i = 0; i < 8; i++) acc[i] = 0ull;
#pragma unroll 4
    for (int m = 0; m < 64; m++) {
        ull cc = splat2(Ks[m * 65 + d]);
        const ull* vp = (const ull*)&Vs[m * STR + e0];
#pragma unroll
        for (int t = 0; t < 8; t++) acc[t] = fma2(cc, vp[t], acc[t]);
    }
    ull* op = (ull*)&g_kv[(size_t)blockIdx.x * 4096 + d * 64 + e0];
#pragma unroll
    for (int t = 0; t < 8; t++) op[t] = acc[t];
}

// ================= K4: totals over key blocks =================
__global__ void total_kernel() {
    const int bh = blockIdx.x;
    const int o = blockIdx.y * 256 + threadIdx.x;
    const float* p = &g_kv[(size_t)bh * NBLK * 4096 + o];
    float s = 0.f;
#pragma unroll 8
    for (int b = 0; b < NBLK; b++) s += p[(size_t)b * 4096];
    g_kvtot[bh * 4096 + o] = s;
    if (blockIdx.y == 0 && threadIdx.x < 64) {
        float z = 0.f;
#pragma unroll
        for (int b = 0; b < NBLK; b++) z += g_z[((size_t)bh * NBLK + b) * 64 + threadIdx.x];
        g_ztot[bh * 64 + threadIdx.x] = z;
    }
}

// ================= K5: fused sparse attention + linear path + projection =================
// grid BH*NBLK, block 128, 87.3 KB dynamic smem.
// 8x4 per-thread tile: all GEMM inner loops are 2 broadcast LDS.128 + 1 LDS.128 + 16 FFMA2.
// Softmax is unstabilized exp (scores bounded ~|10|), row sums reduced once after the j loop.
__global__ void __launch_bounds__(128) attn_kernel(
    const float* __restrict__ q, const float* __restrict__ k, const float* __restrict__ v,
    const float* __restrict__ Wl, const float* __restrict__ bl, float* __restrict__ out)
{
    extern __shared__ float sm[];
    float* Qt  = sm;                 // [d][r]  q transposed; later phi(q) transposed
    float* Kt  = Qt + 64 * STR;      // [d][c]  K^T per block; later KVns [d][e]
    float* Vs  = Kt + 64 * STR;      // [c][e]  V natural
    float* Ps  = Vs + 64 * STR;      // [r][c]  P natural; later Ol natural [r][d]
    float* Wlt = Ps + 64 * STR;      // [d][e]  Wlt[d*STR+e] = W_l[e][d]
    float* zns = Wlt + 64 * STR;     // 64
    int*   lut = (int*)(zns + 64);   // 8

    const int tid = threadIdx.x;
    const int bh = blockIdx.x >> 6, qi = blockIdx.x & 63;
    const int tr = tid >> 4, tc = tid & 15;
    const int r0 = tr * 8, c0 = tc * 4;
    const size_t qbase = ((size_t)bh * LSEQ + qi * 64) * DDIM;

    // load Q (transposed) and W_l (transposed)
    for (int i = tid; i < 4096; i += 128) {
        int a = i >> 6, b = i & 63;
        Qt[b * STR + a]  = q[qbase + i];
        Wlt[b * STR + a] = Wl[i];
    }
    if (tid < TK) lut[tid] = g_lut[(bh * 64 + qi) * TK + tid];
    __syncthreads();

    float psum[8];
    ull O01[8], O23[8];
#pragma unroll
    for (int i = 0; i < 8; i++) { psum[i] = 0.f; O01[i] = 0ull; O23[i] = 0ull; }

    for (int j = 0; j < TK; j++) {
        const size_t kbase = ((size_t)bh * LSEQ + lut[j] * 64) * DDIM;
        // K transposed + V natural
        for (int i = tid; i < 4096; i += 128) {
            int c = i >> 6, d = i & 63;
            Kt[d * STR + c] = k[kbase + i];
        }
        for (int i4 = tid; i4 < 1024; i4 += 128) {
            int c = i4 >> 4, e = (i4 & 15) * 4;
            *(float4*)&Vs[c * STR + e] = *(const float4*)&v[kbase + c * 64 + e];
        }
        __syncthreads();

        // S = Q K^T  (8 rows x 4 cols per thread)
        ull s01[8], s23[8];
#pragma unroll
        for (int i = 0; i < 8; i++) { s01[i] = 0ull; s23[i] = 0ull; }
#pragma unroll 8
        for (int d = 0; d < 64; d++) {
            float4 qa = *(const float4*)&Qt[d * STR + r0];
            float4 qb = *(const float4*)&Qt[d * STR + r0 + 4];
            ulonglong2 kk = *(const ulonglong2*)&Kt[d * STR + c0];
            ull w;
            w = splat2(qa.x); s01[0] = fma2(w, kk.x, s01[0]); s23[0] = fma2(w, kk.y, s23[0]);
            w = splat2(qa.y); s01[1] = fma2(w, kk.x, s01[1]); s23[1] = fma2(w, kk.y, s23[1]);
            w = splat2(qa.z); s01[2] = fma2(w, kk.x, s01[2]); s23[2] = fma2(w, kk.y, s23[2]);
            w = splat2(qa.w); s01[3] = fma2(w, kk.x, s01[3]); s23[3] = fma2(w, kk.y, s23[3]);
            w = splat2(qb.x); s01[4] = fma2(w, kk.x, s01[4]); s23[4] = fma2(w, kk.y, s23[4]);
            w = splat2(qb.y); s01[5] = fma2(w, kk.x, s01[5]); s23[5] = fma2(w, kk.y, s23[5]);
            w = splat2(qb.z); s01[6] = fma2(w, kk.x, s01[6]); s23[6] = fma2(w, kk.y, s23[6]);
            w = splat2(qb.w); s01[7] = fma2(w, kk.x, s01[7]); s23[7] = fma2(w, kk.y, s23[7]);
        }
        // unnormalized exp + partial row sums + store P
#pragma unroll
        for (int ri = 0; ri < 8; ri++) {
            float a, b, c2, d2;
            upk2(s01[ri], a, b); upk2(s23[ri], c2, d2);
            float pa = __expf(a * ATT_SCALE), pb = __expf(b * ATT_SCALE);
            float pc = __expf(c2 * ATT_SCALE), pd = __expf(d2 * ATT_SCALE);
            psum[ri] += (pa + pb) + (pc + pd);
            *(float4*)&Ps[(r0 + ri) * STR + c0] = make_float4(pa, pb, pc, pd);
        }
        __syncthreads();

        // O += P V
#pragma unroll 4
        for (int c = 0; c < 64; c++) {
            ulonglong2 vv = *(const ulonglong2*)&Vs[c * STR + c0];
            const float* pr = &Ps[c];
            ull w;
            w = splat2(pr[(r0 + 0) * STR]); O01[0] = fma2(w, vv.x, O01[0]); O23[0] = fma2(w, vv.y, O23[0]);
            w = splat2(pr[(r0 + 1) * STR]); O01[1] = fma2(w, vv.x, O01[1]); O23[1] = fma2(w, vv.y, O23[1]);
            w = splat2(pr[(r0 + 2) * STR]); O01[2] = fma2(w, vv.x, O01[2]); O23[2] = fma2(w, vv.y, O23[2]);
            w = splat2(pr[(r0 + 3) * STR]); O01[3] = fma2(w, vv.x, O01[3]); O23[3] = fma2(w, vv.y, O23[3]);
            w = splat2(pr[(r0 + 4) * STR]); O01[4] = fma2(w, vv.x, O01[4]); O23[4] = fma2(w, vv.y, O23[4]);
            w = splat2(pr[(r0 + 5) * STR]); O01[5] = fma2(w, vv.x, O01[5]); O23[5] = fma2(w, vv.y, O23[5]);
            w = splat2(pr[(r0 + 6) * STR]); O01[6] = fma2(w, vv.x, O01[6]); O23[6] = fma2(w, vv.y, O23[6]);
            w = splat2(pr[(r0 + 7) * STR]); O01[7] = fma2(w, vv.x, O01[7]); O23[7] = fma2(w, vv.y, O23[7]);
        }
        __syncthreads();
    }

    // full row sums (across the 16 lanes of each row) and normalization
#pragma unroll
    for (int ri = 0; ri < 8; ri++) {
        float ps = psum[ri];
        ps += __shfl_xor_sync(0xffffffffu, ps, 1);
        ps += __shfl_xor_sync(0xffffffffu, ps, 2);
        ps += __shfl_xor_sync(0xffffffffu, ps, 4);
        ps += __shfl_xor_sync(0xffffffffu, ps, 8);
        ull inv = splat2(1.f / ps);
        O01[ri] = mul2(O01[ri], inv); O23[ri] = mul2(O23[ri], inv);
    }

    // ---------- linear path ----------
    // KVns = kvtot - sum(selected kv) -> Kt natural [d][e]
    {
        const float* kvt = &g_kvtot[bh * 4096];
        const float* kvb = &g_kv[(size_t)bh * NBLK * 4096];
        const int o0 = tid * 32;
#pragma unroll
        for (int u = 0; u < 8; u++) {
            int o = o0 + 4 * u;
            float4 a = *(const float4*)&kvt[o];
#pragma unroll
            for (int j = 0; j < TK; j++) {
                float4 b4 = *(const float4*)&kvb[(size_t)lut[j] * 4096 + o];
                a.x -= b4.x; a.y -= b4.y; a.z -= b4.z; a.w -= b4.w;
            }
            *(float4*)&Kt[(o >> 6) * STR + (o & 63)] = a;
        }
    }
    if (tid >= 64) {
        const int r = tid - 64;
        float zz = g_ztot[bh * 64 + r];
#pragma unroll
        for (int j = 0; j < TK; j++) zz -= g_z[((size_t)bh * NBLK + lut[j]) * 64 + r];
        zns[r] = zz;
    } else {
        // phi(q): in-place softmax over head dim, column tid of Qt
        const int r = tid;
        float mx = -1e30f;
#pragma unroll
        for (int d = 0; d < 64; d++) mx = fmaxf(mx, Qt[d * STR + r]);
        float s = 0.f;
#pragma unroll
        for (int d = 0; d < 64; d++) { float e2 = __expf(Qt[d * STR + r] - mx); Qt[d * STR + r] = e2; s += e2; }
        float inv = 1.f / s;
#pragma unroll
        for (int d = 0; d < 64; d++) Qt[d * STR + r] *= inv;
    }
    __syncthreads();

    // num = phi(q) @ KVns ; den = phi(q).zns ; Ol = num/(den+1e-6) -> Ps natural
    {
        ull n01[8], n23[8]; float den[8];
#pragma unroll
        for (int i = 0; i < 8; i++) { n01[i] = 0ull; n23[i] = 0ull; den[i] = 0.f; }
#pragma unroll 8
        for (int d = 0; d < 64; d++) {
            float4 qa = *(const float4*)&Qt[d * STR + r0];
            float4 qb = *(const float4*)&Qt[d * STR + r0 + 4];
            ulonglong2 kk = *(const ulonglong2*)&Kt[d * STR + c0];
            float zd = zns[d];
            ull w;
            w = splat2(qa.x); n01[0] = fma2(w, kk.x, n01[0]); n23[0] = fma2(w, kk.y, n23[0]); den[0] = fmaf(qa.x, zd, den[0]);
            w = splat2(qa.y); n01[1] = fma2(w, kk.x, n01[1]); n23[1] = fma2(w, kk.y, n23[1]); den[1] = fmaf(qa.y, zd, den[1]);
            w = splat2(qa.z); n01[2] = fma2(w, kk.x, n01[2]); n23[2] = fma2(w, kk.y, n23[2]); den[2] = fmaf(qa.z, zd, den[2]);
            w = splat2(qa.w); n01[3] = fma2(w, kk.x, n01[3]); n23[3] = fma2(w, kk.y, n23[3]); den[3] = fmaf(qa.w, zd, den[3]);
            w = splat2(qb.x); n01[4] = fma2(w, kk.x, n01[4]); n23[4] = fma2(w, kk.y, n23[4]); den[4] = fmaf(qb.x, zd, den[4]);
            w = splat2(qb.y); n01[5] = fma2(w, kk.x, n01[5]); n23[5] = fma2(w, kk.y, n23[5]); den[5] = fmaf(qb.y, zd, den[5]);
            w = splat2(qb.z); n01[6] = fma2(w, kk.x, n01[6]); n23[6] = fma2(w, kk.y, n23[6]); den[6] = fmaf(qb.z, zd, den[6]);
            w = splat2(qb.w); n01[7] = fma2(w, kk.x, n01[7]); n23[7] = fma2(w, kk.y, n23[7]); den[7] = fmaf(qb.w, zd, den[7]);
        }
#pragma unroll
        for (int ri = 0; ri < 8; ri++) {
            float inv = 1.f / (den[ri] + 1e-6f);
            float a, b, c2, d2; upk2(n01[ri], a, b); upk2(n23[ri], c2, d2);
            *(float4*)&Ps[(r0 + ri) * STR + c0] = make_float4(a * inv, b * inv, c2 * inv, d2 * inv);
        }
    }
    __syncthreads();

    // out = O_sparse + Ol @ Wl^T + bl
#pragma unroll 4
    for (int d = 0; d < 64; d++) {
        ulonglong2 ww = *(const ulonglong2*)&Wlt[d * STR + c0];
        const float* orow = &Ps[d];
        ull w;
        w = splat2(orow[(r0 + 0) * STR]); O01[0] = fma2(w, ww.x, O01[0]); O23[0] = fma2(w, ww.y, O23[0]);
        w = splat2(orow[(r0 + 1) * STR]); O01[1] = fma2(w, ww.x, O01[1]); O23[1] = fma2(w, ww.y, O23[1]);
        w = splat2(orow[(r0 + 2) * STR]); O01[2] = fma2(w, ww.x, O01[2]); O23[2] = fma2(w, ww.y, O23[2]);
        w = splat2(orow[(r0 + 3) * STR]); O01[3] = fma2(w, ww.x, O01[3]); O23[3] = fma2(w, ww.y, O23[3]);
        w = splat2(orow[(r0 + 4) * STR]); O01[4] = fma2(w, ww.x, O01[4]); O23[4] = fma2(w, ww.y, O23[4]);
        w = splat2(orow[(r0 + 5) * STR]); O01[5] = fma2(w, ww.x, O01[5]); O23[5] = fma2(w, ww.y, O23[5]);
        w = splat2(orow[(r0 + 6) * STR]); O01[6] = fma2(w, ww.x, O01[6]); O23[6] = fma2(w, ww.y, O23[6]);
        w = splat2(orow[(r0 + 7) * STR]); O01[7] = fma2(w, ww.x, O01[7]); O23[7] = fma2(w, ww.y, O23[7]);
    }
    {
        float4 bv = *(const float4*)&bl[c0];
#pragma unroll
        for (int ri = 0; ri < 8; ri++) {
            float a, b, c2, d2; upk2(O01[ri], a, b); upk2(O23[ri], c2, d2);
            *(float4*)&out[qbase + (size_t)(r0 + ri) * 64 + c0] =
                make_float4(a + bv.x, b + bv.y, c2 + bv.z, d2 + bv.w);
        }
    }
}

// ================= launcher =================
extern "C" void kernel_launch(void* const* d_in, const int* in_sizes, int n_in,
                              void* d_out, int out_size) {
    const float* q  = (const float*)d_in[0];
    const float* k  = (const float*)d_in[1];
    const float* v  = (const float*)d_in[2];
    const float* Wl = (const float*)d_in[3];
    const float* bl = (const float*)d_in[4];
    float* out = (float*)d_out;

    const int smem_bytes = (5 * 64 * STR + 64 + 8) * (int)sizeof(float);  // 87,328 B
    cudaFuncSetAttribute(attn_kernel, cudaFuncAttributeMaxDynamicSharedMemorySize, smem_bytes);

    pool_kernel<<<dim3(BH * NBLK, 2), 64>>>(q, k);
    topk_kernel<<<BH * NBLK, 64>>>();
    kv_kernel<<<BH * NBLK, 256>>>(k, v);
    total_kernel<<<dim3(BH, 16), 256>>>();
    attn_kernel<<<BH * NBLK, 128, smem_bytes>>>(q, k, v, Wl, bl, out);
}

// round 6
// speedup vs baseline: 1.1917x; 1.1671x over previous
#include <cuda_runtime.h>
#include <cuda_bf16.h>
#include <cstdint>

#define BH    32
#define LSEQ  4096
#define DDIM  64
#define NBLK  64
#define TK    6
#define STR   68          // fp32 epilogue stride
#define PSTR  33          // bf16x2 pair-row stride (u32 units)
#define ATT_SCALE 0.125f

typedef unsigned long long ull;
typedef unsigned int u32;

// ---------------- f32x2 packed helpers (epilogue / kv kernel) ----------------
__device__ __forceinline__ ull fma2(ull a, ull b, ull c) {
    ull d; asm("fma.rn.f32x2 %0,%1,%2,%3;" : "=l"(d) : "l"(a), "l"(b), "l"(c)); return d;
}
__device__ __forceinline__ ull splat2(float a) {
    ull r; asm("mov.b64 %0,{%1,%1};" : "=l"(r) : "f"(a)); return r;
}
__device__ __forceinline__ void upk2(ull x, float& a, float& b) {
    asm("mov.b64 {%0,%1},%2;" : "=f"(a), "=f"(b) : "l"(x));
}

// ---------------- bf16 split helpers ----------------
// pack: low half = lo-arg (even k), high half = hi-arg (odd k)
__device__ __forceinline__ u32 packbf(float e, float o) {
    u32 r; asm("cvt.rn.bf16x2.f32 %0,%1,%2;" : "=r"(r) : "f"(o), "f"(e)); return r;
}
__device__ __forceinline__ float lo_f(u32 u) { return __uint_as_float(u << 16); }
__device__ __forceinline__ float hi_f(u32 u) { return __uint_as_float(u & 0xffff0000u); }
// split a pair (f0,f1) into hi bf16x2 + residual-lo bf16x2
__device__ __forceinline__ void split2(float f0, float f1, u32& h, u32& l) {
    h = packbf(f0, f1);
    l = packbf(f0 - lo_f(h), f1 - hi_f(h));
}

// ---------------- mma.sync m16n8k16 bf16 ----------------
__device__ __forceinline__ void mma16816(float* c, const u32* a, const u32* b) {
    asm("mma.sync.aligned.m16n8k16.row.col.f32.bf16.bf16.f32 "
        "{%0,%1,%2,%3},{%4,%5,%6,%7},{%8,%9},{%0,%1,%2,%3};"
        : "+f"(c[0]), "+f"(c[1]), "+f"(c[2]), "+f"(c[3])
        : "r"(a[0]), "r"(a[1]), "r"(a[2]), "r"(a[3]), "r"(b[0]), "r"(b[1]));
}

// ---------------- device scratch ----------------
__device__ float g_qmean[BH * NBLK * DDIM];
__device__ float g_kmean[BH * NBLK * DDIM];
__device__ int   g_lut[BH * NBLK * TK];
__device__ float g_kv[(size_t)BH * NBLK * DDIM * DDIM];
__device__ float g_z[BH * NBLK * DDIM];
__device__ float g_kvtot[BH * DDIM * DDIM];
__device__ float g_ztot[BH * DDIM];

// ================= K1: fused mean-pool + per-block kv/z =================
// grid BH*NBLK, block 256
__global__ void __launch_bounds__(256) kvpool_kernel(
    const float* __restrict__ q, const float* __restrict__ k, const float* __restrict__ v)
{
    __shared__ __align__(16) float Ks[64 * 65];
    __shared__ __align__(16) float Vs[64 * STR];
    const int tid = threadIdx.x;
    const size_t base = (size_t)blockIdx.x * 4096;
    for (int i = tid; i < 4096; i += 256)
        Ks[(i >> 6) * 65 + (i & 63)] = k[base + i];
    for (int i4 = tid; i4 < 1024; i4 += 256) {
        int c = i4 >> 4, e = (i4 & 15) * 4;
        *(float4*)&Vs[c * STR + e] = *(const float4*)&v[base + c * 64 + e];
    }
    __syncthreads();
    // block means (k from smem, q from gmem)
    if (tid < 64) {
        float s = 0.f;
#pragma unroll
        for (int m = 0; m < 64; m++) s += Ks[m * 65 + tid];
        g_kmean[blockIdx.x * 64 + tid] = s * (1.f / 64.f);
    } else if (tid < 128) {
        const int d = tid - 64;
        const float* p = q + base + d;
        float s = 0.f;
#pragma unroll
        for (int m = 0; m < 64; m++) s += p[m * 64];
        g_qmean[blockIdx.x * 64 + d] = s * (1.f / 64.f);
    }
    __syncthreads();
    if (tid < 64) {                       // phi(k): row softmax
        float* row = &Ks[tid * 65];
        float mx = -1e30f;
#pragma unroll
        for (int i = 0; i < 64; i++) mx = fmaxf(mx, row[i]);
        float s = 0.f;
#pragma unroll
        for (int i = 0; i < 64; i++) { float e = __expf(row[i] - mx); row[i] = e; s += e; }
        float inv = 1.f / s;
#pragma unroll
        for (int i = 0; i < 64; i++) row[i] *= inv;
    }
    __syncthreads();
    if (tid < 64) {                       // z column sums
        float s = 0.f;
#pragma unroll
        for (int m = 0; m < 64; m++) s += Ks[m * 65 + tid];
        g_z[(size_t)blockIdx.x * 64 + tid] = s;
    }
    const int d = tid >> 2, e0 = (tid & 3) * 16;
    ull acc[8];
#pragma unroll
    for (int i = 0; i < 8; i++) acc[i] = 0ull;
#pragma unroll 4
    for (int m = 0; m < 64; m++) {
        ull cc = splat2(Ks[m * 65 + d]);
        const ull* vp = (const ull*)&Vs[m * STR + e0];
#pragma unroll
        for (int t = 0; t < 8; t++) acc[t] = fma2(cc, vp[t], acc[t]);
    }
    ull* op = (ull*)&g_kv[(size_t)blockIdx.x * 4096 + d * 64 + e0];
#pragma unroll
    for (int t = 0; t < 8; t++) op[t] = acc[t];
}

// ================= K2: block scores + top-6 =================
__global__ void topk_kernel() {
    __shared__ float km[64 * 65];
    __shared__ float qv[64];
    __shared__ float sc[64];
    const int bh = blockIdx.x >> 6, qi = blockIdx.x & 63;
    const int tid = threadIdx.x;
    for (int i = tid; i < 4096; i += 64) km[(i >> 6) * 65 + (i & 63)] = g_kmean[bh * 4096 + i];
    qv[tid] = g_qmean[bh * 4096 + qi * 64 + tid];
    __syncthreads();
    float s = 0.f;
#pragma unroll
    for (int d = 0; d < 64; d++) s += qv[d] * km[tid * 65 + d];
    sc[tid] = s;
    __syncthreads();
    if (tid == 0) {
        int* lp = &g_lut[(bh * 64 + qi) * TK];
#pragma unroll
        for (int t = 0; t < TK; t++) {
            float best = -1e38f; int bi = 0;
            for (int i = 0; i < 64; i++) { if (sc[i] > best) { best = sc[i]; bi = i; } }
            lp[t] = bi; sc[bi] = -1e38f;
        }
    }
}

// ================= K3: totals over key blocks =================
__global__ void total_kernel() {
    const int bh = blockIdx.x;
    const int o = blockIdx.y * 256 + threadIdx.x;
    const float* p = &g_kv[(size_t)bh * NBLK * 4096 + o];
    float s = 0.f;
#pragma unroll 8
    for (int b = 0; b < NBLK; b++) s += p[(size_t)b * 4096];
    g_kvtot[bh * 4096 + o] = s;
    if (blockIdx.y == 0 && threadIdx.x < 64) {
        float z = 0.f;
#pragma unroll
        for (int b = 0; b < NBLK; b++) z += g_z[((size_t)bh * NBLK + b) * 64 + threadIdx.x];
        g_ztot[bh * 64 + threadIdx.x] = z;
    }
}

// ================= K4: fused sparse attention (tensor cores) + linear + proj =================
// grid BH*NBLK, block 128 (4 warps, 16 rows each), ~104 KB dynamic smem.
// QK^T and PV run on mma.sync bf16 with 3-way split (hi*hi + hi*lo + lo*hi).
__global__ void __launch_bounds__(128) attn_kernel(
    const float* __restrict__ q, const float* __restrict__ k, const float* __restrict__ v,
    const float* __restrict__ Wl, const float* __restrict__ bl, float* __restrict__ out)
{
    extern __shared__ __align__(16) unsigned char smraw[];
    // persistent: Q bf16x2 pairs hi/lo  [64 rows][33 pairs] u32
    u32* Qh = (u32*)smraw;                     // 8448 B
    u32* Ql = Qh + 64 * PSTR;                  // 8448 B
    unsigned char* U = (unsigned char*)(Ql + 64 * PSTR);  // union region
    // mainloop layout in U
    u32* Kh = (u32*)U;                         // [key][pair d]   8448
    u32* Kl = Kh + 64 * PSTR;
    u32* Vh = Kl + 64 * PSTR;                  // [e][pair key]   8448
    u32* Vl = Vh + 64 * PSTR;
    // epilogue layout in U (overlays the above after the j-loop)
    float* OS   = (float*)U;                   // [r][e]   64*68
    float* PhiT = OS   + 64 * STR;             // [d][r]
    float* KVns = PhiT + 64 * STR;             // [d][e]
    float* OlS  = KVns + 64 * STR;             // [r][d]
    float* Wlt  = OlS  + 64 * STR;             // [d][e]
    float* zns  = Wlt  + 64 * STR;             // 64
    __shared__ int lut[8];

    const int tid  = threadIdx.x;
    const int lane = tid & 31;
    const int R    = (tid >> 5) * 16;          // warp row base
    const int g    = lane >> 2, t = lane & 3;
    const int bh = blockIdx.x >> 6, qi = blockIdx.x & 63;
    const size_t qbase = ((size_t)bh * LSEQ + qi * 64) * DDIM;

    if (tid < TK) lut[tid] = g_lut[(bh * 64 + qi) * TK + tid];
    // build Q hi/lo pairs: id -> (row c, pair p)
#pragma unroll
    for (int i = 0; i < 16; i++) {
        int id = tid + 128 * i;
        int c = id >> 5, p = id & 31;
        float2 f = *(const float2*)&q[qbase + c * 64 + 2 * p];
        u32 h, l; split2(f.x, f.y, h, l);
        Qh[c * PSTR + p] = h; Ql[c * PSTR + p] = l;
    }

    float O[8][4];
#pragma unroll
    for (int i = 0; i < 8; i++) { O[i][0] = O[i][1] = O[i][2] = O[i][3] = 0.f; }
    float rs0 = 0.f, rs1 = 0.f;

    for (int j = 0; j < TK; j++) {
        __syncthreads();   // prior iter's mma reads done before overwrite
        const size_t kbase = ((size_t)bh * LSEQ + lut[j] * 64) * DDIM;
        // K: [key c][pair p over d]
#pragma unroll
        for (int i = 0; i < 16; i++) {
            int id = tid + 128 * i;
            int c = id >> 5, p = id & 31;
            float2 f = *(const float2*)&k[kbase + c * 64 + 2 * p];
            u32 h, l; split2(f.x, f.y, h, l);
            Kh[c * PSTR + p] = h; Kl[c * PSTR + p] = l;
        }
        // V transposed pairs: [e][pair pp over keys]
#pragma unroll
        for (int i = 0; i < 16; i++) {
            int id = tid + 128 * i;
            int e = id & 63, pp = id >> 6;
            float a = v[kbase + (2 * pp) * 64 + e];
            float b = v[kbase + (2 * pp + 1) * 64 + e];
            u32 h, l; split2(a, b, h, l);
            Vh[e * PSTR + pp] = h; Vl[e * PSTR + pp] = l;
        }
        __syncthreads();

        // ---- S = Q K^T via mma (8 n-tiles of 8 keys) ----
        float S[8][4];
#pragma unroll
        for (int i = 0; i < 8; i++) { S[i][0] = S[i][1] = S[i][2] = S[i][3] = 0.f; }
        const int ao0 = (R + g) * PSTR + t, ao1 = (R + g + 8) * PSTR + t;
#pragma unroll
        for (int s = 0; s < 4; s++) {
            u32 ah[4], al[4];
            ah[0] = Qh[ao0 + s * 8];     ah[1] = Qh[ao1 + s * 8];
            ah[2] = Qh[ao0 + s * 8 + 4]; ah[3] = Qh[ao1 + s * 8 + 4];
            al[0] = Ql[ao0 + s * 8];     al[1] = Ql[ao1 + s * 8];
            al[2] = Ql[ao0 + s * 8 + 4]; al[3] = Ql[ao1 + s * 8 + 4];
#pragma unroll
            for (int nt = 0; nt < 8; nt++) {
                int bo = (nt * 8 + g) * PSTR + s * 8 + t;
                u32 bhv[2] = { Kh[bo], Kh[bo + 4] };
                u32 blv[2] = { Kl[bo], Kl[bo + 4] };
                mma16816(S[nt], ah, bhv);
                mma16816(S[nt], ah, blv);
                mma16816(S[nt], al, bhv);
            }
        }
        // ---- exp (unnormalized) + pack P into A-fragments ----
        u32 ph01[8], ph23[8], pl01[8], pl23[8];
#pragma unroll
        for (int nt = 0; nt < 8; nt++) {
            float p0 = __expf(S[nt][0] * ATT_SCALE);
            float p1 = __expf(S[nt][1] * ATT_SCALE);
            float p2 = __expf(S[nt][2] * ATT_SCALE);
            float p3 = __expf(S[nt][3] * ATT_SCALE);
            rs0 += p0 + p1; rs1 += p2 + p3;
            split2(p0, p1, ph01[nt], pl01[nt]);
            split2(p2, p3, ph23[nt], pl23[nt]);
        }
        // ---- O += P V via mma ----
#pragma unroll
        for (int s = 0; s < 4; s++) {
            u32 ah[4] = { ph01[2 * s], ph23[2 * s], ph01[2 * s + 1], ph23[2 * s + 1] };
            u32 al[4] = { pl01[2 * s], pl23[2 * s], pl01[2 * s + 1], pl23[2 * s + 1] };
#pragma unroll
            for (int et = 0; et < 8; et++) {
                int bo = (et * 8 + g) * PSTR + s * 8 + t;
                u32 bhv[2] = { Vh[bo], Vh[bo + 4] };
                u32 blv[2] = { Vl[bo], Vl[bo + 4] };
                mma16816(O[et], ah, bhv);
                mma16816(O[et], ah, blv);
                mma16816(O[et], al, bhv);
            }
        }
    }
    __syncthreads();   // all warps done with K/V region before OS overlays it

    // normalize + store O_sparse to OS
    rs0 += __shfl_xor_sync(0xffffffffu, rs0, 1); rs0 += __shfl_xor_sync(0xffffffffu, rs0, 2);
    rs1 += __shfl_xor_sync(0xffffffffu, rs1, 1); rs1 += __shfl_xor_sync(0xffffffffu, rs1, 2);
    const float inv0 = 1.f / rs0, inv1 = 1.f / rs1;
#pragma unroll
    for (int et = 0; et < 8; et++) {
        int c = et * 8 + 2 * t;
        OS[(R + g) * STR + c]         = O[et][0] * inv0;
        OS[(R + g) * STR + c + 1]     = O[et][1] * inv0;
        OS[(R + g + 8) * STR + c]     = O[et][2] * inv1;
        OS[(R + g + 8) * STR + c + 1] = O[et][3] * inv1;
    }

    // ---------- epilogue buffers ----------
    // W_l transposed
    for (int i = tid; i < 4096; i += 128) {
        int a = i >> 6, b = i & 63;
        Wlt[b * STR + a] = Wl[i];
    }
    // KVns = kvtot - sum(selected kv)
    {
        const float* kvt = &g_kvtot[bh * 4096];
        const float* kvb = &g_kv[(size_t)bh * NBLK * 4096];
        const int o0 = tid * 32;
#pragma unroll
        for (int u = 0; u < 8; u++) {
            int o = o0 + 4 * u;
            float4 a = *(const float4*)&kvt[o];
#pragma unroll
            for (int j = 0; j < TK; j++) {
                float4 b4 = *(const float4*)&kvb[(size_t)lut[j] * 4096 + o];
                a.x -= b4.x; a.y -= b4.y; a.z -= b4.z; a.w -= b4.w;
            }
            *(float4*)&KVns[(o >> 6) * STR + (o & 63)] = a;
        }
    }
    if (tid >= 64) {
        const int r = tid - 64;
        float zz = g_ztot[bh * 64 + r];
#pragma unroll
        for (int j = 0; j < TK; j++) zz -= g_z[((size_t)bh * NBLK + lut[j]) * 64 + r];
        zns[r] = zz;
    } else {
        // phi(q) for row r, from hi+lo pairs; store transposed into PhiT[d][r]
        const int r = tid;
        float mx = -1e30f;
#pragma unroll
        for (int p = 0; p < 32; p++) {
            u32 h = Qh[r * PSTR + p], l = Ql[r * PSTR + p];
            float e0 = lo_f(h) + lo_f(l), e1 = hi_f(h) + hi_f(l);
            mx = fmaxf(mx, fmaxf(e0, e1));
        }
        float s = 0.f;
#pragma unroll
        for (int p = 0; p < 32; p++) {
            u32 h = Qh[r * PSTR + p], l = Ql[r * PSTR + p];
            float e0 = __expf(lo_f(h) + lo_f(l) - mx);
            float e1 = __expf(hi_f(h) + hi_f(l) - mx);
            PhiT[(2 * p) * STR + r] = e0; PhiT[(2 * p + 1) * STR + r] = e1;
            s += e0 + e1;
        }
        float inv = 1.f / s;
#pragma unroll
        for (int d = 0; d < 64; d++) PhiT[d * STR + r] *= inv;
    }
    __syncthreads();

    // thread tile for fp32 epilogue: 8 rows x 4 cols
    const int tr = tid >> 4, tc = tid & 15;
    const int r0 = tr * 8, c0 = tc * 4;

    // Ol = (phi(q) @ KVns) / (phi(q).zns + 1e-6) -> OlS
    {
        ull n01[8], n23[8]; float den[8];
#pragma unroll
        for (int i = 0; i < 8; i++) { n01[i] = 0ull; n23[i] = 0ull; den[i] = 0.f; }
#pragma unroll 8
        for (int d = 0; d < 64; d++) {
            float4 qa = *(const float4*)&PhiT[d * STR + r0];
            float4 qb = *(const float4*)&PhiT[d * STR + r0 + 4];
            ulonglong2 kk = *(const ulonglong2*)&KVns[d * STR + c0];
            float zd = zns[d];
            ull w;
            w = splat2(qa.x); n01[0] = fma2(w, kk.x, n01[0]); n23[0] = fma2(w, kk.y, n23[0]); den[0] = fmaf(qa.x, zd, den[0]);
            w = splat2(qa.y); n01[1] = fma2(w, kk.x, n01[1]); n23[1] = fma2(w, kk.y, n23[1]); den[1] = fmaf(qa.y, zd, den[1]);
            w = splat2(qa.z); n01[2] = fma2(w, kk.x, n01[2]); n23[2] = fma2(w, kk.y, n23[2]); den[2] = fmaf(qa.z, zd, den[2]);
            w = splat2(qa.w); n01[3] = fma2(w, kk.x, n01[3]); n23[3] = fma2(w, kk.y, n23[3]); den[3] = fmaf(qa.w, zd, den[3]);
            w = splat2(qb.x); n01[4] = fma2(w, kk.x, n01[4]); n23[4] = fma2(w, kk.y, n23[4]); den[4] = fmaf(qb.x, zd, den[4]);
            w = splat2(qb.y); n01[5] = fma2(w, kk.x, n01[5]); n23[5] = fma2(w, kk.y, n23[5]); den[5] = fmaf(qb.y, zd, den[5]);
            w = splat2(qb.z); n01[6] = fma2(w, kk.x, n01[6]); n23[6] = fma2(w, kk.y, n23[6]); den[6] = fmaf(qb.z, zd, den[6]);
            w = splat2(qb.w); n01[7] = fma2(w, kk.x, n01[7]); n23[7] = fma2(w, kk.y, n23[7]); den[7] = fmaf(qb.w, zd, den[7]);
        }
#pragma unroll
        for (int ri = 0; ri < 8; ri++) {
            float inv = 1.f / (den[ri] + 1e-6f);
            float a, b, c2, d2; upk2(n01[ri], a, b); upk2(n23[ri], c2, d2);
            *(float4*)&OlS[(r0 + ri) * STR + c0] = make_float4(a * inv, b * inv, c2 * inv, d2 * inv);
        }
    }
    __syncthreads();

    // out = OS + Ol @ Wl^T + bl
    {
        ull a01[8], a23[8];
#pragma unroll
        for (int i = 0; i < 8; i++) { a01[i] = 0ull; a23[i] = 0ull; }
#pragma unroll 4
        for (int d = 0; d < 64; d++) {
            ulonglong2 ww = *(const ulonglong2*)&Wlt[d * STR + c0];
            const float* orow = &OlS[d];
            ull w;
            w = splat2(orow[(r0 + 0) * STR]); a01[0] = fma2(w, ww.x, a01[0]); a23[0] = fma2(w, ww.y, a23[0]);
            w = splat2(orow[(r0 + 1) * STR]); a01[1] = fma2(w, ww.x, a01[1]); a23[1] = fma2(w, ww.y, a23[1]);
            w = splat2(orow[(r0 + 2) * STR]); a01[2] = fma2(w, ww.x, a01[2]); a23[2] = fma2(w, ww.y, a23[2]);
            w = splat2(orow[(r0 + 3) * STR]); a01[3] = fma2(w, ww.x, a01[3]); a23[3] = fma2(w, ww.y, a23[3]);
            w = splat2(orow[(r0 + 4) * STR]); a01[4] = fma2(w, ww.x, a01[4]); a23[4] = fma2(w, ww.y, a23[4]);
            w = splat2(orow[(r0 + 5) * STR]); a01[5] = fma2(w, ww.x, a01[5]); a23[5] = fma2(w, ww.y, a23[5]);
            w = splat2(orow[(r0 + 6) * STR]); a01[6] = fma2(w, ww.x, a01[6]); a23[6] = fma2(w, ww.y, a23[6]);
            w = splat2(orow[(r0 + 7) * STR]); a01[7] = fma2(w, ww.x, a01[7]); a23[7] = fma2(w, ww.y, a23[7]);
        }
        float4 bv = *(const float4*)&bl[c0];
#pragma unroll
        for (int ri = 0; ri < 8; ri++) {
            float a, b, c2, d2; upk2(a01[ri], a, b); upk2(a23[ri], c2, d2);
            float4 osv = *(const float4*)&OS[(r0 + ri) * STR + c0];
            *(float4*)&out[qbase + (size_t)(r0 + ri) * 64 + c0] =
                make_float4(a + bv.x + osv.x, b + bv.y + osv.y,
                            c2 + bv.z + osv.z, d2 + bv.w + osv.w);
        }
    }
}

// ================= launcher =================
extern "C" void kernel_launch(void* const* d_in, const int* in_sizes, int n_in,
                              void* d_out, int out_size) {
    const float* q  = (const float*)d_in[0];
    const float* k  = (const float*)d_in[1];
    const float* v  = (const float*)d_in[2];
    const float* Wl = (const float*)d_in[3];
    const float* bl = (const float*)d_in[4];
    float* out = (float*)d_out;

    // Qh+Ql pairs (2*8448) + union( mainloop 4*8448 , epilogue 5*64*STR*4 + 256 )
    const int union_bytes = 5 * 64 * STR * 4 + 256;           // 87,296
    const int smem_bytes  = 2 * 64 * PSTR * 4 + union_bytes;  // 104,192
    cudaFuncSetAttribute(attn_kernel, cudaFuncAttributeMaxDynamicSharedMemorySize, smem_bytes);

    kvpool_kernel<<<BH * NBLK, 256>>>(q, k, v);
    topk_kernel<<<BH * NBLK, 64>>>();
    total_kernel<<<dim3(BH, 16), 256>>>();
    attn_kernel<<<BH * NBLK, 128, smem_bytes>>>(q, k, v, Wl, bl, out);
}

// round 7
// speedup vs baseline: 1.4788x; 1.2409x over previous
#include <cuda_runtime.h>
#include <cuda_bf16.h>
#include <cstdint>

#define BH    32
#define LSEQ  4096
#define DDIM  64
#define NBLK  64
#define TK    6
#define STR   68          // fp32 epilogue stride
#define PSTR  36          // bf16x2 pair-row stride in u32 (36 mod 32 = 4 -> conflict-free frags)
#define ATT_SCALE 0.125f

typedef unsigned long long ull;
typedef unsigned int u32;

// ---------------- f32x2 packed helpers ----------------
__device__ __forceinline__ ull fma2(ull a, ull b, ull c) {
    ull d; asm("fma.rn.f32x2 %0,%1,%2,%3;" : "=l"(d) : "l"(a), "l"(b), "l"(c)); return d;
}
__device__ __forceinline__ ull splat2(float a) {
    ull r; asm("mov.b64 %0,{%1,%1};" : "=l"(r) : "f"(a)); return r;
}
__device__ __forceinline__ void upk2(ull x, float& a, float& b) {
    asm("mov.b64 {%0,%1},%2;" : "=f"(a), "=f"(b) : "l"(x));
}

// ---------------- bf16 split helpers ----------------
__device__ __forceinline__ u32 packbf(float e, float o) {
    u32 r; asm("cvt.rn.bf16x2.f32 %0,%1,%2;" : "=r"(r) : "f"(o), "f"(e)); return r;
}
__device__ __forceinline__ float lo_f(u32 u) { return __uint_as_float(u << 16); }
__device__ __forceinline__ float hi_f(u32 u) { return __uint_as_float(u & 0xffff0000u); }
__device__ __forceinline__ void split2(float f0, float f1, u32& h, u32& l) {
    h = packbf(f0, f1);
    l = packbf(f0 - lo_f(h), f1 - hi_f(h));
}

// ---------------- mma.sync m16n8k16 bf16 ----------------
__device__ __forceinline__ void mma16816(float* c, const u32* a, const u32* b) {
    asm("mma.sync.aligned.m16n8k16.row.col.f32.bf16.bf16.f32 "
        "{%0,%1,%2,%3},{%4,%5,%6,%7},{%8,%9},{%0,%1,%2,%3};"
        : "+f"(c[0]), "+f"(c[1]), "+f"(c[2]), "+f"(c[3])
        : "r"(a[0]), "r"(a[1]), "r"(a[2]), "r"(a[3]), "r"(b[0]), "r"(b[1]));
}

// ---------------- device scratch ----------------
__device__ float g_qmean[BH * NBLK * DDIM];
__device__ float g_kmean[BH * NBLK * DDIM];
__device__ int   g_lut[BH * NBLK * TK];
__device__ float g_kv[(size_t)BH * NBLK * DDIM * DDIM];
__device__ float g_z[BH * NBLK * DDIM];
__device__ float g_kvtot[BH * DDIM * DDIM];
__device__ float g_ztot[BH * DDIM];

// ================= K1: fused mean-pool + per-block kv/z =================
__global__ void __launch_bounds__(256) kvpool_kernel(
    const float* __restrict__ q, const float* __restrict__ k, const float* __restrict__ v)
{
    __shared__ __align__(16) float Ks[64 * 65];
    __shared__ __align__(16) float Vs[64 * STR];
    const int tid = threadIdx.x;
    const size_t base = (size_t)blockIdx.x * 4096;
    for (int i = tid; i < 4096; i += 256)
        Ks[(i >> 6) * 65 + (i & 63)] = k[base + i];
    for (int i4 = tid; i4 < 1024; i4 += 256) {
        int c = i4 >> 4, e = (i4 & 15) * 4;
        *(float4*)&Vs[c * STR + e] = *(const float4*)&v[base + c * 64 + e];
    }
    __syncthreads();
    if (tid < 64) {
        float s = 0.f;
#pragma unroll
        for (int m = 0; m < 64; m++) s += Ks[m * 65 + tid];
        g_kmean[blockIdx.x * 64 + tid] = s * (1.f / 64.f);
    } else if (tid < 128) {
        const int d = tid - 64;
        const float* p = q + base + d;
        float s = 0.f;
#pragma unroll
        for (int m = 0; m < 64; m++) s += p[m * 64];
        g_qmean[blockIdx.x * 64 + d] = s * (1.f / 64.f);
    }
    __syncthreads();
    if (tid < 64) {                       // phi(k): row softmax
        float* row = &Ks[tid * 65];
        float mx = -1e30f;
#pragma unroll
        for (int i = 0; i < 64; i++) mx = fmaxf(mx, row[i]);
        float s = 0.f;
#pragma unroll
        for (int i = 0; i < 64; i++) { float e = __expf(row[i] - mx); row[i] = e; s += e; }
        float inv = 1.f / s;
#pragma unroll
        for (int i = 0; i < 64; i++) row[i] *= inv;
    }
    __syncthreads();
    if (tid < 64) {
        float s = 0.f;
#pragma unroll
        for (int m = 0; m < 64; m++) s += Ks[m * 65 + tid];
        g_z[(size_t)blockIdx.x * 64 + tid] = s;
    }
    const int d = tid >> 2, e0 = (tid & 3) * 16;
    ull acc[8];
#pragma unroll
    for (int i = 0; i < 8; i++) acc[i] = 0ull;
#pragma unroll 4
    for (int m = 0; m < 64; m++) {
        ull cc = splat2(Ks[m * 65 + d]);
        const ull* vp = (const ull*)&Vs[m * STR + e0];
#pragma unroll
        for (int t = 0; t < 8; t++) acc[t] = fma2(cc, vp[t], acc[t]);
    }
    ull* op = (ull*)&g_kv[(size_t)blockIdx.x * 4096 + d * 64 + e0];
#pragma unroll
    for (int t = 0; t < 8; t++) op[t] = acc[t];
}

// ================= K2: block scores + top-6 (warp argmax) =================
__global__ void topk_kernel() {
    __shared__ float km[64 * 65];
    __shared__ float qv[64];
    __shared__ float sc[64];
    const int bh = blockIdx.x >> 6, qi = blockIdx.x & 63;
    const int tid = threadIdx.x;
    for (int i = tid; i < 4096; i += 64) km[(i >> 6) * 65 + (i & 63)] = g_kmean[bh * 4096 + i];
    qv[tid] = g_qmean[bh * 4096 + qi * 64 + tid];
    __syncthreads();
    float s = 0.f;
#pragma unroll
    for (int d = 0; d < 64; d++) s += qv[d] * km[tid * 65 + d];
    sc[tid] = s;
    __syncthreads();
    if (tid < 32) {
        float s0 = sc[tid], s1 = sc[tid + 32];
        int* lp = &g_lut[(bh * 64 + qi) * TK];
#pragma unroll
        for (int t = 0; t < TK; t++) {
            // local best of the two owned scores (prefer lower index on tie)
            float m = (s1 > s0) ? s1 : s0;
            int idx = (s1 > s0) ? (tid + 32) : tid;
#pragma unroll
            for (int off = 16; off; off >>= 1) {
                float om = __shfl_xor_sync(0xffffffffu, m, off);
                int oi = __shfl_xor_sync(0xffffffffu, idx, off);
                if (om > m || (om == m && oi < idx)) { m = om; idx = oi; }
            }
            if (tid == 0) lp[t] = idx;
            if (idx == tid) s0 = -1e38f;
            if (idx == tid + 32) s1 = -1e38f;
        }
    }
}

// ================= K3: totals over key blocks =================
__global__ void total_kernel() {
    const int bh = blockIdx.x;
    const int o = blockIdx.y * 256 + threadIdx.x;
    const float* p = &g_kv[(size_t)bh * NBLK * 4096 + o];
    float s = 0.f;
#pragma unroll 8
    for (int b = 0; b < NBLK; b++) s += p[(size_t)b * 4096];
    g_kvtot[bh * 4096 + o] = s;
    if (blockIdx.y == 0 && threadIdx.x < 64) {
        float z = 0.f;
#pragma unroll
        for (int b = 0; b < NBLK; b++) z += g_z[((size_t)bh * NBLK + b) * 64 + threadIdx.x];
        g_ztot[bh * 64 + threadIdx.x] = z;
    }
}

// ================= K4: fused sparse attention (tensor cores) + linear + proj =================
// grid BH*NBLK, block 128 (4 warps). PSTR=36 -> conflict-free fragment LDS.
// V tile XOR-swizzled (pp ^ ((e>>3)&3)) so transpose STS is conflict-free too.
__global__ void __launch_bounds__(128) attn_kernel(
    const float* __restrict__ q, const float* __restrict__ k, const float* __restrict__ v,
    const float* __restrict__ Wl, const float* __restrict__ bl, float* __restrict__ out)
{
    extern __shared__ __align__(16) unsigned char smraw[];
    u32* Qh = (u32*)smraw;                     // [row][pair] 64*36 u32
    u32* Ql = Qh + 64 * PSTR;
    unsigned char* U = (unsigned char*)(Ql + 64 * PSTR);  // union region
    // mainloop layout
    u32* Kh = (u32*)U;                         // [key][pair d]
    u32* Kl = Kh + 64 * PSTR;
    u32* Vh = Kl + 64 * PSTR;                  // [e][pair key ^ swz]
    u32* Vl = Vh + 64 * PSTR;
    // epilogue layout (overlays after the j-loop)
    float* OS   = (float*)U;                   // [r][e]
    float* PhiT = OS   + 64 * STR;             // [d][r]
    float* KVns = PhiT + 64 * STR;             // [d][e]
    float* OlS  = KVns + 64 * STR;             // [r][d]
    float* Wlt  = OlS  + 64 * STR;             // [d][e]
    float* zns  = Wlt  + 64 * STR;             // 64
    __shared__ int lut[8];

    const int tid  = threadIdx.x;
    const int lane = tid & 31;
    const int R    = (tid >> 5) * 16;
    const int g    = lane >> 2, t = lane & 3;
    const int bh = blockIdx.x >> 6, qi = blockIdx.x & 63;
    const size_t qbase = ((size_t)bh * LSEQ + qi * 64) * DDIM;

    if (tid < TK) lut[tid] = g_lut[(bh * 64 + qi) * TK + tid];
#pragma unroll
    for (int i = 0; i < 16; i++) {
        int id = tid + 128 * i;
        int c = id >> 5, p = id & 31;
        float2 f = *(const float2*)&q[qbase + c * 64 + 2 * p];
        u32 h, l; split2(f.x, f.y, h, l);
        Qh[c * PSTR + p] = h; Ql[c * PSTR + p] = l;
    }

    float O[8][4];
#pragma unroll
    for (int i = 0; i < 8; i++) { O[i][0] = O[i][1] = O[i][2] = O[i][3] = 0.f; }
    float rs0 = 0.f, rs1 = 0.f;

    for (int j = 0; j < TK; j++) {
        __syncthreads();
        const size_t kbase = ((size_t)bh * LSEQ + lut[j] * 64) * DDIM;
#pragma unroll
        for (int i = 0; i < 16; i++) {
            int id = tid + 128 * i;
            int c = id >> 5, p = id & 31;
            float2 f = *(const float2*)&k[kbase + c * 64 + 2 * p];
            u32 h, l; split2(f.x, f.y, h, l);
            Kh[c * PSTR + p] = h; Kl[c * PSTR + p] = l;
        }
#pragma unroll
        for (int i = 0; i < 16; i++) {
            int id = tid + 128 * i;
            int e = id & 63, pp = id >> 6;
            float a = v[kbase + (2 * pp) * 64 + e];
            float b = v[kbase + (2 * pp + 1) * 64 + e];
            u32 h, l; split2(a, b, h, l);
            int psw = pp ^ ((e >> 3) & 3);
            Vh[e * PSTR + psw] = h; Vl[e * PSTR + psw] = l;
        }
        __syncthreads();

        // ---- S = Q K^T ----
        float S[8][4];
#pragma unroll
        for (int i = 0; i < 8; i++) { S[i][0] = S[i][1] = S[i][2] = S[i][3] = 0.f; }
        const int ao0 = (R + g) * PSTR + t, ao1 = (R + g + 8) * PSTR + t;
#pragma unroll
        for (int s = 0; s < 4; s++) {
            u32 ah[4], al[4];
            ah[0] = Qh[ao0 + s * 8];     ah[1] = Qh[ao1 + s * 8];
            ah[2] = Qh[ao0 + s * 8 + 4]; ah[3] = Qh[ao1 + s * 8 + 4];
            al[0] = Ql[ao0 + s * 8];     al[1] = Ql[ao1 + s * 8];
            al[2] = Ql[ao0 + s * 8 + 4]; al[3] = Ql[ao1 + s * 8 + 4];
#pragma unroll
            for (int nt = 0; nt < 8; nt++) {
                int bo = (nt * 8 + g) * PSTR + s * 8 + t;
                u32 bhv[2] = { Kh[bo], Kh[bo + 4] };
                u32 blv[2] = { Kl[bo], Kl[bo + 4] };
                mma16816(S[nt], ah, bhv);
                mma16816(S[nt], ah, blv);
                mma16816(S[nt], al, bhv);
            }
        }
        // ---- exp + pack P ----
        u32 ph01[8], ph23[8], pl01[8], pl23[8];
#pragma unroll
        for (int nt = 0; nt < 8; nt++) {
            float p0 = __expf(S[nt][0] * ATT_SCALE);
            float p1 = __expf(S[nt][1] * ATT_SCALE);
            float p2 = __expf(S[nt][2] * ATT_SCALE);
            float p3 = __expf(S[nt][3] * ATT_SCALE);
            rs0 += p0 + p1; rs1 += p2 + p3;
            split2(p0, p1, ph01[nt], pl01[nt]);
            split2(p2, p3, ph23[nt], pl23[nt]);
        }
        // ---- O += P V ----
#pragma unroll
        for (int s = 0; s < 4; s++) {
            u32 ah[4] = { ph01[2 * s], ph23[2 * s], ph01[2 * s + 1], ph23[2 * s + 1] };
            u32 al[4] = { pl01[2 * s], pl23[2 * s], pl01[2 * s + 1], pl23[2 * s + 1] };
#pragma unroll
            for (int et = 0; et < 8; et++) {
                int x = et & 3;
                int bo = (et * 8 + g) * PSTR + s * 8 + (t ^ x);
                u32 bhv[2] = { Vh[bo], Vh[bo + 4] };
                u32 blv[2] = { Vl[bo], Vl[bo + 4] };
                mma16816(O[et], ah, bhv);
                mma16816(O[et], ah, blv);
                mma16816(O[et], al, bhv);
            }
        }
    }
    __syncthreads();

    rs0 += __shfl_xor_sync(0xffffffffu, rs0, 1); rs0 += __shfl_xor_sync(0xffffffffu, rs0, 2);
    rs1 += __shfl_xor_sync(0xffffffffu, rs1, 1); rs1 += __shfl_xor_sync(0xffffffffu, rs1, 2);
    const float inv0 = 1.f / rs0, inv1 = 1.f / rs1;
#pragma unroll
    for (int et = 0; et < 8; et++) {
        int c = et * 8 + 2 * t;
        OS[(R + g) * STR + c]         = O[et][0] * inv0;
        OS[(R + g) * STR + c + 1]     = O[et][1] * inv0;
        OS[(R + g + 8) * STR + c]     = O[et][2] * inv1;
        OS[(R + g + 8) * STR + c + 1] = O[et][3] * inv1;
    }

    // ---------- epilogue ----------
    for (int i = tid; i < 4096; i += 128) {
        int a = i >> 6, b = i & 63;
        Wlt[b * STR + a] = Wl[i];
    }
    {
        const float* kvt = &g_kvtot[bh * 4096];
        const float* kvb = &g_kv[(size_t)bh * NBLK * 4096];
        const int o0 = tid * 32;
#pragma unroll
        for (int u = 0; u < 8; u++) {
            int o = o0 + 4 * u;
            float4 a = *(const float4*)&kvt[o];
#pragma unroll
            for (int j = 0; j < TK; j++) {
                float4 b4 = *(const float4*)&kvb[(size_t)lut[j] * 4096 + o];
                a.x -= b4.x; a.y -= b4.y; a.z -= b4.z; a.w -= b4.w;
            }
            *(float4*)&KVns[(o >> 6) * STR + (o & 63)] = a;
        }
    }
    if (tid >= 64) {
        const int r = tid - 64;
        float zz = g_ztot[bh * 64 + r];
#pragma unroll
        for (int j = 0; j < TK; j++) zz -= g_z[((size_t)bh * NBLK + lut[j]) * 64 + r];
        zns[r] = zz;
    } else {
        const int r = tid;
        float mx = -1e30f;
#pragma unroll
        for (int p = 0; p < 32; p++) {
            u32 h = Qh[r * PSTR + p], l = Ql[r * PSTR + p];
            float e0 = lo_f(h) + lo_f(l), e1 = hi_f(h) + hi_f(l);
            mx = fmaxf(mx, fmaxf(e0, e1));
        }
        float s = 0.f;
#pragma unroll
        for (int p = 0; p < 32; p++) {
            u32 h = Qh[r * PSTR + p], l = Ql[r * PSTR + p];
            float e0 = __expf(lo_f(h) + lo_f(l) - mx);
            float e1 = __expf(hi_f(h) + hi_f(l) - mx);
            PhiT[(2 * p) * STR + r] = e0; PhiT[(2 * p + 1) * STR + r] = e1;
            s += e0 + e1;
        }
        float inv = 1.f / s;
#pragma unroll
        for (int d = 0; d < 64; d++) PhiT[d * STR + r] *= inv;
    }
    __syncthreads();

    const int tr = tid >> 4, tc = tid & 15;
    const int r0 = tr * 8, c0 = tc * 4;

    // Ol = (phi(q) @ KVns) / (phi(q).zns + 1e-6)
    {
        ull n01[8], n23[8]; float den[8];
#pragma unroll
        for (int i = 0; i < 8; i++) { n01[i] = 0ull; n23[i] = 0ull; den[i] = 0.f; }
#pragma unroll 8
        for (int d = 0; d < 64; d++) {
            float4 qa = *(const float4*)&PhiT[d * STR + r0];
            float4 qb = *(const float4*)&PhiT[d * STR + r0 + 4];
            ulonglong2 kk = *(const ulonglong2*)&KVns[d * STR + c0];
            float zd = zns[d];
            ull w;
            w = splat2(qa.x); n01[0] = fma2(w, kk.x, n01[0]); n23[0] = fma2(w, kk.y, n23[0]); den[0] = fmaf(qa.x, zd, den[0]);
            w = splat2(qa.y); n01[1] = fma2(w, kk.x, n01[1]); n23[1] = fma2(w, kk.y, n23[1]); den[1] = fmaf(qa.y, zd, den[1]);
            w = splat2(qa.z); n01[2] = fma2(w, kk.x, n01[2]); n23[2] = fma2(w, kk.y, n23[2]); den[2] = fmaf(qa.z, zd, den[2]);
            w = splat2(qa.w); n01[3] = fma2(w, kk.x, n01[3]); n23[3] = fma2(w, kk.y, n23[3]); den[3] = fmaf(qa.w, zd, den[3]);
            w = splat2(qb.x); n01[4] = fma2(w, kk.x, n01[4]); n23[4] = fma2(w, kk.y, n23[4]); den[4] = fmaf(qb.x, zd, den[4]);
            w = splat2(qb.y); n01[5] = fma2(w, kk.x, n01[5]); n23[5] = fma2(w, kk.y, n23[5]); den[5] = fmaf(qb.y, zd, den[5]);
            w = splat2(qb.z); n01[6] = fma2(w, kk.x, n01[6]); n23[6] = fma2(w, kk.y, n23[6]); den[6] = fmaf(qb.z, zd, den[6]);
            w = splat2(qb.w); n01[7] = fma2(w, kk.x, n01[7]); n23[7] = fma2(w, kk.y, n23[7]); den[7] = fmaf(qb.w, zd, den[7]);
        }
#pragma unroll
        for (int ri = 0; ri < 8; ri++) {
            float inv = 1.f / (den[ri] + 1e-6f);
            float a, b, c2, d2; upk2(n01[ri], a, b); upk2(n23[ri], c2, d2);
            *(float4*)&OlS[(r0 + ri) * STR + c0] = make_float4(a * inv, b * inv, c2 * inv, d2 * inv);
        }
    }
    __syncthreads();

    // out = OS + Ol @ Wl^T + bl
    {
        ull a01[8], a23[8];
#pragma unroll
        for (int i = 0; i < 8; i++) { a01[i] = 0ull; a23[i] = 0ull; }
#pragma unroll 4
        for (int d = 0; d < 64; d++) {
            ulonglong2 ww = *(const ulonglong2*)&Wlt[d * STR + c0];
            const float* orow = &OlS[d];
            ull w;
            w = splat2(orow[(r0 + 0) * STR]); a01[0] = fma2(w, ww.x, a01[0]); a23[0] = fma2(w, ww.y, a23[0]);
            w = splat2(orow[(r0 + 1) * STR]); a01[1] = fma2(w, ww.x, a01[1]); a23[1] = fma2(w, ww.y, a23[1]);
            w = splat2(orow[(r0 + 2) * STR]); a01[2] = fma2(w, ww.x, a01[2]); a23[2] = fma2(w, ww.y, a23[2]);
            w = splat2(orow[(r0 + 3) * STR]); a01[3] = fma2(w, ww.x, a01[3]); a23[3] = fma2(w, ww.y, a23[3]);
            w = splat2(orow[(r0 + 4) * STR]); a01[4] = fma2(w, ww.x, a01[4]); a23[4] = fma2(w, ww.y, a23[4]);
            w = splat2(orow[(r0 + 5) * STR]); a01[5] = fma2(w, ww.x, a01[5]); a23[5] = fma2(w, ww.y, a23[5]);
            w = splat2(orow[(r0 + 6) * STR]); a01[6] = fma2(w, ww.x, a01[6]); a23[6] = fma2(w, ww.y, a23[6]);
            w = splat2(orow[(r0 + 7) * STR]); a01[7] = fma2(w, ww.x, a01[7]); a23[7] = fma2(w, ww.y, a23[7]);
        }
        float4 bv = *(const float4*)&bl[c0];
#pragma unroll
        for (int ri = 0; ri < 8; ri++) {
            float a, b, c2, d2; upk2(a01[ri], a, b); upk2(a23[ri], c2, d2);
            float4 osv = *(const float4*)&OS[(r0 + ri) * STR + c0];
            *(float4*)&out[qbase + (size_t)(r0 + ri) * 64 + c0] =
                make_float4(a + bv.x + osv.x, b + bv.y + osv.y,
                            c2 + bv.z + osv.z, d2 + bv.w + osv.w);
        }
    }
}

// ================= launcher =================
extern "C" void kernel_launch(void* const* d_in, const int* in_sizes, int n_in,
                              void* d_out, int out_size) {
    const float* q  = (const float*)d_in[0];
    const float* k  = (const float*)d_in[1];
    const float* v  = (const float*)d_in[2];
    const float* Wl = (const float*)d_in[3];
    const float* bl = (const float*)d_in[4];
    float* out = (float*)d_out;

    const int union_bytes = 5 * 64 * STR * 4 + 256;           // 87,296 (>= mainloop 36,864)
    const int smem_bytes  = 2 * 64 * PSTR * 4 + union_bytes;  // 105,728
    cudaFuncSetAttribute(attn_kernel, cudaFuncAttributeMaxDynamicSharedMemorySize, smem_bytes);

    kvpool_kernel<<<BH * NBLK, 256>>>(q, k, v);
    topk_kernel<<<BH * NBLK, 64>>>();
    total_kernel<<<dim3(BH, 16), 256>>>();
    attn_kernel<<<BH * NBLK, 128, smem_bytes>>>(q, k, v, Wl, bl, out);
}